// round 8
// baseline (speedup 1.0000x reference)
#include <cuda_runtime.h>
#include <cuda_fp16.h>
#include <math.h>
#include <stdint.h>

// ===========================================================================
// ImplicitMap_fExtrator — fp16 3-term-split GEMM via mma.sync.m16n8k16.f16.
// Round 8: SMEM tiles repacked as [hi 64B | lo 64B] per 128B row with full
// SW128 swizzle -> conflict-free ldmatrix (round-7 layout had 2-way conflicts
// from 64B rows). Kc=32 x 3 stages (96KB), 2 CTAs/SM, 1 sync/iter.
// ===========================================================================

#define NPTS   16384
#define NROWS  65536
#define PITCH  960

__device__ __half g_hiA[(size_t)NROWS * PITCH];
__device__ __half g_loA[(size_t)NROWS * PITCH];
__device__ __half g_hiB[(size_t)NROWS * PITCH];
__device__ __half g_loB[(size_t)NROWS * PITCH];
__device__ __half g_Whi[5600000];
__device__ __half g_Wlo[5600000];

static const int    LCIN [11] = {259,515,512,512,576,576,768,768,768,960,960};
static const int    LCOUT[11] = {515,512,512,576,576,768,768,768,960,960,896};
static const int    LPIT [11] = {264,520,512,512,576,576,768,768,768,960,960};
static const size_t LWOFF[11] = {0,135960,402200,664344,959256,1291032,1733400,
                                 2323224,2913048,3650328,4571928};

__device__ const int    d_LCIN [11] = {259,515,512,512,576,576,768,768,768,960,960};
__device__ const int    d_LCOUT[11] = {515,512,512,576,576,768,768,768,960,960,896};
__device__ const int    d_LPIT [11] = {264,520,512,512,576,576,768,768,768,960,960};
__device__ const size_t d_LWOFF[11] = {0,135960,402200,664344,959256,1291032,1733400,
                                       2323224,2913048,3650328,4571928};

// ---- PTX helpers ----------------------------------------------------------
__device__ __forceinline__ uint32_t smem_u32(const void* p) {
    uint32_t a;
    asm("{ .reg .u64 t; cvta.to.shared.u64 t, %1; cvt.u32.u64 %0, t; }"
        : "=r"(a) : "l"(p));
    return a;
}
__device__ __forceinline__ void cpa16(uint32_t dst, const void* src, int sz) {
    asm volatile("cp.async.cg.shared.global [%0], [%1], 16, %2;"
                 :: "r"(dst), "l"(src), "r"(sz));
}
__device__ __forceinline__ void cpa_commit() {
    asm volatile("cp.async.commit_group;" ::: "memory");
}
__device__ __forceinline__ void ldsm4(uint32_t* r, uint32_t a) {
    asm volatile("ldmatrix.sync.aligned.m8n8.x4.shared.b16 {%0,%1,%2,%3}, [%4];"
                 : "=r"(r[0]), "=r"(r[1]), "=r"(r[2]), "=r"(r[3]) : "r"(a));
}
__device__ __forceinline__ void mma_f16(float* d, const uint32_t* a,
                                        uint32_t b0, uint32_t b1) {
    asm volatile("mma.sync.aligned.m16n8k16.row.col.f32.f16.f16.f32 "
                 "{%0,%1,%2,%3}, {%4,%5,%6,%7}, {%8,%9}, {%0,%1,%2,%3};"
                 : "+f"(d[0]), "+f"(d[1]), "+f"(d[2]), "+f"(d[3])
                 : "r"(a[0]), "r"(a[1]), "r"(a[2]), "r"(a[3]),
                   "r"(b0), "r"(b1));
}
__device__ __forceinline__ void split2h(float v, __half& h, __half& l) {
    h = __float2half_rn(v);
    l = __float2half_rn(v - __half2float(h));
}

// ---- fused W prep ----------------------------------------------------------
struct WPtrs { const float* w[11]; };

__global__ void prep_all_kernel(WPtrs wp)
{
    int l = blockIdx.y;
    int idx = blockIdx.x * blockDim.x + threadIdx.x;
    int cin = d_LCIN[l];
    int cnt = cin * d_LCOUT[l];
    if (idx >= cnt) return;
    int row = idx / cin, col = idx - row * cin;
    __half h, lo;
    split2h(wp.w[l][idx], h, lo);
    size_t d = d_LWOFF[l] + (size_t)row * d_LPIT[l] + col;
    g_Whi[d] = h;
    g_Wlo[d] = lo;
}

// ---- init ------------------------------------------------------------------
__global__ void init_kernel(const float* __restrict__ inp,
                            const float* __restrict__ lat,
                            float* __restrict__ out_con)
{
    int idx = blockIdx.x * blockDim.x + threadIdx.x;   // NPTS*259
    if (idx >= NPTS * 259) return;
    int p = idx / 259;
    int c = idx - p * 259;
    int b = p >> 13;
    float v = (c < 3) ? inp[p * 3 + c] : lat[b * 256 + (c - 3)];
    out_con[idx] = v;
    size_t r0 = (size_t)(4 * p) * PITCH + c;
    __half h, l;
    split2h(v, h, l);
    g_hiA[r0] = h; g_loA[r0] = l;
    #pragma unroll
    for (int ch = 1; ch <= 3; ch++) {
        float gv = (c == ch - 1) ? 1.0f : 0.0f;
        size_t r = (size_t)(4 * p + ch) * PITCH + c;
        g_hiA[r] = __float2half_rn(gv);
        g_loA[r] = __float2half_rn(0.0f);
    }
}

// ---- fused layer: CTA 128x128, Kc=32, 3 stages, SW128 hi|lo-packed rows ---
#define STAGES 3
#define A_OFF 0
#define B_OFF 16384
#define STG_SZ 32768
#define SMEM_BYTES (STAGES * STG_SZ)
#define SWZ(o) ((o) ^ (((o) >> 3) & 0x70))

__global__ void __launch_bounds__(256, 2)
layer_kernel(const float* __restrict__ bias, int cin, int cout,
             int wpitch, size_t woff, int flip)
{
    extern __shared__ char smem[];
    __shared__ float bias_s[128];
    const uint32_t sb = smem_u32(smem);
    const int t = threadIdx.x;
    const int lane = t & 31, wid = t >> 5;

    const __half* __restrict__ Xhi = flip ? g_hiB : g_hiA;
    const __half* __restrict__ Xlo = flip ? g_loB : g_loA;
    __half* __restrict__ Yhi = flip ? g_hiA : g_hiB;
    __half* __restrict__ Ylo = flip ? g_loA : g_loB;
    const __half* __restrict__ Wh = g_Whi + woff;
    const __half* __restrict__ Wl = g_Wlo + woff;

    const int cblk = blockIdx.x * 128;
    const int nblk = blockIdx.y * 128;

    if (t < 128) {
        int c = cblk + t;
        bias_s[t] = (c < cout) ? __ldg(bias + c) : 0.f;
    }

    const int ktiles = (cin + 31) >> 5;

    // row layout: 128 rows x 128B; bytes [0,64) = hi k-halves, [64,128) = lo.
    // 1024 granules per tile (A and B each), 4 per thread per tile.
    auto load_stage = [&](int s, int kt) {
        const uint32_t base = sb + (uint32_t)s * STG_SZ;
        const int k0 = kt << 5;
        #pragma unroll
        for (int i = 0; i < 4; i++) {                  // A tile
            int li = t + (i << 8);
            int r = li >> 3, g = li & 7;
            int kk = k0 + (g & 3) * 8;
            int rem = cin - kk;
            int sz = rem >= 8 ? 16 : (rem > 0 ? rem * 2 : 0);
            const __half* src = (g < 4) ? Xhi : Xlo;
            cpa16(base + A_OFF + SWZ((uint32_t)(r * 128 + g * 16)),
                  src + (size_t)(nblk + r) * PITCH + kk, sz);
        }
        #pragma unroll
        for (int i = 0; i < 4; i++) {                  // B tile
            int li = t + (i << 8);
            int r = li >> 3, g = li & 7;
            int row = cblk + r;
            int kk = k0 + (g & 3) * 8;
            int rem = cin - kk;
            int sz = (row < cout) ? (rem >= 8 ? 16 : (rem > 0 ? rem * 2 : 0)) : 0;
            const __half* src = (g < 4) ? Wh : Wl;
            cpa16(base + B_OFF + SWZ((uint32_t)(r * 128 + g * 16)),
                  src + (size_t)row * wpitch + kk, sz);
        }
        cpa_commit();
    };

    // fragment addressing (128B rows, SW128 — conflict-free)
    const int wm = wid >> 2, wn = wid & 3;       // warp tile 64(M) x 32(N)
    const int seg = lane >> 3, i7 = lane & 7;
    uint32_t aR[4], aX[4];
    #pragma unroll
    for (int mi = 0; mi < 4; mi++) {
        int r = wm * 64 + mi * 16 + (seg & 1) * 8 + i7;
        aR[mi] = (uint32_t)(r * 128);
        aX[mi] = (uint32_t)((r & 7) << 4);
    }
    const uint32_t akd = (uint32_t)((seg >> 1) * 16);
    uint32_t bR[2], bX[2];
    #pragma unroll
    for (int np = 0; np < 2; np++) {
        int r = wn * 32 + np * 16 + (seg >> 1) * 8 + i7;
        bR[np] = (uint32_t)(r * 128);
        bX[np] = (uint32_t)((r & 7) << 4);
    }
    const uint32_t bkd = (uint32_t)((seg & 1) * 16);

    float acc[4][4][4];
    #pragma unroll
    for (int mi = 0; mi < 4; mi++)
        #pragma unroll
        for (int ni = 0; ni < 4; ni++)
            #pragma unroll
            for (int r = 0; r < 4; r++) acc[mi][ni][r] = 0.f;

    auto compute = [&](int s) {
        const uint32_t base = sb + (uint32_t)s * STG_SZ;
        #pragma unroll
        for (int st = 0; st < 2; st++) {
            const uint32_t kb = (uint32_t)(st * 32);     // byte col in hi half
            uint32_t Ah[4][4], Bh[2][4];
            #pragma unroll
            for (int mi = 0; mi < 4; mi++)
                ldsm4(Ah[mi], base + A_OFF + aR[mi] + ((kb + akd) ^ aX[mi]));
            #pragma unroll
            for (int np = 0; np < 2; np++)
                ldsm4(Bh[np], base + B_OFF + bR[np] + ((kb + bkd) ^ bX[np]));
            #pragma unroll
            for (int mi = 0; mi < 4; mi++)
                #pragma unroll
                for (int ni = 0; ni < 4; ni++)
                    mma_f16(acc[mi][ni], Ah[mi],
                            Bh[ni >> 1][(ni & 1) * 2], Bh[ni >> 1][(ni & 1) * 2 + 1]);
            {   // term 2: Al*Bh (lo half lives at byte col +64)
                uint32_t Al[4][4];
                #pragma unroll
                for (int mi = 0; mi < 4; mi++)
                    ldsm4(Al[mi], base + A_OFF + aR[mi] + ((64 + kb + akd) ^ aX[mi]));
                #pragma unroll
                for (int mi = 0; mi < 4; mi++)
                    #pragma unroll
                    for (int ni = 0; ni < 4; ni++)
                        mma_f16(acc[mi][ni], Al[mi],
                                Bh[ni >> 1][(ni & 1) * 2], Bh[ni >> 1][(ni & 1) * 2 + 1]);
            }
            {   // term 3: Ah*Bl
                uint32_t Bl[2][4];
                #pragma unroll
                for (int np = 0; np < 2; np++)
                    ldsm4(Bl[np], base + B_OFF + bR[np] + ((64 + kb + bkd) ^ bX[np]));
                #pragma unroll
                for (int mi = 0; mi < 4; mi++)
                    #pragma unroll
                    for (int ni = 0; ni < 4; ni++)
                        mma_f16(acc[mi][ni], Ah[mi],
                                Bl[ni >> 1][(ni & 1) * 2], Bl[ni >> 1][(ni & 1) * 2 + 1]);
            }
        }
    };

    // ---- 3-stage pipeline, one barrier per iteration -----------------------
    load_stage(0, 0);
    if (ktiles > 1) load_stage(1, 1); else cpa_commit();
    for (int kt = 0; kt < ktiles; kt++) {
        asm volatile("cp.async.wait_group 1;" ::: "memory");
        __syncthreads();
        int nf = kt + 2;
        if (nf < ktiles) load_stage(nf % STAGES, nf); else cpa_commit();
        compute(kt % STAGES);
    }

    // ---- epilogue ----------------------------------------------------------
    const unsigned FULL = 0xffffffffu;
    const int srcl = lane & ~12;
    const bool is_x = (lane & 12) == 0;
    const int q = lane >> 2, c2 = (lane & 3) * 2;
    #pragma unroll
    for (int mi = 0; mi < 4; mi++) {
        int r0 = nblk + wm * 64 + mi * 16 + q;
        __half* yh0 = Yhi + (size_t)r0 * PITCH;
        __half* yl0 = Ylo + (size_t)r0 * PITCH;
        __half* yh1 = yh0 + (size_t)8 * PITCH;
        __half* yl1 = yl0 + (size_t)8 * PITCH;
        #pragma unroll
        for (int ni = 0; ni < 4; ni++) {
            int nloc = wn * 32 + ni * 8 + c2;
            int cg = cblk + nloc;
            float bv0 = bias_s[nloc], bv1 = bias_s[nloc + 1];
            const float* d = acc[mi][ni];
            #pragma unroll
            for (int rr = 0; rr < 2; rr++) {
                float d0 = d[rr * 2], d1 = d[rr * 2 + 1];
                float z0 = __shfl_sync(FULL, d0, srcl);
                float z1 = __shfl_sync(FULL, d1, srcl);
                float A0 = 100.f * (z0 + bv0);
                float A1 = 100.f * (z1 + bv1);
                float sp0 = 0.f, sg0 = 0.f, sp1 = 0.f, sg1 = 0.f;
                if (is_x) {
                    float e0 = __expf(-fabsf(A0)), e1 = __expf(-fabsf(A1));
                    sp0 = (fmaxf(A0, 0.f) + __logf(1.f + e0)) * 0.01f;
                    sp1 = (fmaxf(A1, 0.f) + __logf(1.f + e1)) * 0.01f;
                    float i0 = __fdividef(1.f, 1.f + e0);
                    float i1 = __fdividef(1.f, 1.f + e1);
                    sg0 = (A0 >= 0.f) ? i0 : e0 * i0;
                    sg1 = (A1 >= 0.f) ? i1 : e1 * i1;
                }
                sg0 = __shfl_sync(FULL, sg0, srcl);
                sg1 = __shfl_sync(FULL, sg1, srcl);
                float y0 = is_x ? sp0 : sg0 * d0;
                float y1 = is_x ? sp1 : sg1 * d1;
                __half h0, l0, h1, l1;
                split2h(y0, h0, l0);
                split2h(y1, h1, l1);
                __half* yh = rr ? yh1 : yh0;
                __half* yl = rr ? yl1 : yl0;
                if (cg + 1 < cout) {
                    uint32_t hp = (uint32_t)__half_as_ushort(h0)
                                | ((uint32_t)__half_as_ushort(h1) << 16);
                    uint32_t lp = (uint32_t)__half_as_ushort(l0)
                                | ((uint32_t)__half_as_ushort(l1) << 16);
                    *(uint32_t*)(yh + cg) = hp;
                    *(uint32_t*)(yl + cg) = lp;
                } else if (cg < cout) {
                    yh[cg] = h0;
                    yl[cg] = l0;
                }
            }
        }
    }
}

// ---- final layer: cout=1 dot product, warp per state row ------------------
__global__ void final_kernel(const float* __restrict__ W,
                             const float* __restrict__ bias,
                             float* __restrict__ out)
{
    int gw = (blockIdx.x * blockDim.x + threadIdx.x) >> 5;
    int lane = threadIdx.x & 31;
    if (gw >= NROWS) return;
    const __half* hp = g_hiB + (size_t)gw * PITCH;
    const __half* lp = g_loB + (size_t)gw * PITCH;
    float s = 0.f;
    for (int i = lane; i < 112; i += 32) {       // 112 * 8 = 896 channels
        uint4 hv = *(const uint4*)(hp + i * 8);
        uint4 lv = *(const uint4*)(lp + i * 8);
        float4 w0 = __ldg((const float4*)W + i * 2);
        float4 w1 = __ldg((const float4*)W + i * 2 + 1);
        const uint32_t* hw = &hv.x;
        const uint32_t* lw = &lv.x;
        float wf2[8] = {w0.x, w0.y, w0.z, w0.w, w1.x, w1.y, w1.z, w1.w};
        #pragma unroll
        for (int qq = 0; qq < 4; qq++) {
            float2 fh = __half22float2(*(const __half2*)&hw[qq]);
            float2 fl = __half22float2(*(const __half2*)&lw[qq]);
            s = fmaf(wf2[2 * qq],     fh.x + fl.x, s);
            s = fmaf(wf2[2 * qq + 1], fh.y + fl.y, s);
        }
    }
    #pragma unroll
    for (int o = 16; o; o >>= 1) s += __shfl_xor_sync(0xffffffffu, s, o);
    if (lane == 0) {
        int ch = gw & 3, p = gw >> 2;
        if (ch == 0) out[p] = s + bias[0];
        else         out[NPTS + 3 * (size_t)p + (ch - 1)] = s;
    }
}

// ---------------------------------------------------------------------------
extern "C" void kernel_launch(void* const* d_in, const int* in_sizes, int n_in,
                              void* d_out, int out_size)
{
    const float* input  = (const float*)d_in[0];
    const float* latent = (const float*)d_in[1];
    float* out = (float*)d_out;
    float* out_con = out + NPTS + NPTS * 3;

    {
        WPtrs wp;
        for (int l = 0; l < 11; l++) wp.w[l] = (const float*)d_in[2 + 2 * l];
        dim3 grid((960 * 960 + 255) / 256, 11);
        prep_all_kernel<<<grid, 256>>>(wp);
    }
    {
        int tot = NPTS * 259;
        init_kernel<<<(tot + 255) / 256, 256>>>(input, latent, out_con);
    }

    cudaFuncSetAttribute(layer_kernel,
                         cudaFuncAttributeMaxDynamicSharedMemorySize, SMEM_BYTES);

    for (int l = 0; l < 11; l++) {
        const float* b = (const float*)d_in[3 + 2 * l];
        dim3 grid((LCOUT[l] + 127) / 128, NROWS / 128);
        layer_kernel<<<grid, 256, SMEM_BYTES>>>(b, LCIN[l], LCOUT[l],
                                                LPIT[l], LWOFF[l], l & 1);
    }

    final_kernel<<<NROWS * 32 / 256, 256>>>((const float*)d_in[24],
                                            (const float*)d_in[25], out);
}